// round 8
// baseline (speedup 1.0000x reference)
#include <cuda_runtime.h>
#include <cuda_bf16.h>
#include <math.h>
#include <stdint.h>

// ---------------- dims ----------------
#define MD 2048
#define NQKV 6144
#define NFF 8192
#define EPS 1e-5f

// ---------------- scratch ----------------
__device__ float g_altx[32 * MD];
__device__ float g_s[32 * MD];
__device__ float g_y[32 * MD];
__device__ float g_imv[32 * MD];
__device__ float g_h[32 * NFF];
__device__ float g_part[8 * 32 * NQKV];   // max: qkv ks=8 -> 1.57M floats

// ---------------- helpers ----------------
#define SWA(o) ((o) ^ ((((o) >> 7) & 3u) << 4))

__device__ __forceinline__ uint32_t smem_u32(const void* p) {
    uint32_t a;
    asm("{ .reg .u64 t; cvta.to.shared.u64 t, %1; cvt.u32.u64 %0, t; }" : "=r"(a) : "l"(p));
    return a;
}

__device__ __forceinline__ uint32_t pack_split(float f0, float f1, uint32_t& lo) {
    __nv_bfloat16 h0 = __float2bfloat16_rn(f0);
    __nv_bfloat16 h1 = __float2bfloat16_rn(f1);
    float r0 = f0 - __bfloat162float(h0);
    float r1 = f1 - __bfloat162float(h1);
    __nv_bfloat16 l0 = __float2bfloat16_rn(r0);
    __nv_bfloat16 l1 = __float2bfloat16_rn(r1);
    lo = (uint32_t)__bfloat16_as_ushort(l0) | ((uint32_t)__bfloat16_as_ushort(l1) << 16);
    return (uint32_t)__bfloat16_as_ushort(h0) | ((uint32_t)__bfloat16_as_ushort(h1) << 16);
}

#define LDSM4(r0, r1, r2, r3, a) \
    asm volatile("ldmatrix.sync.aligned.m8n8.x4.shared.b16 {%0,%1,%2,%3},[%4];" \
        : "=r"(r0), "=r"(r1), "=r"(r2), "=r"(r3) : "r"(a))

#define MMA16816(d, a0, a1, a2, a3, b0, b1) \
    asm volatile("mma.sync.aligned.m16n8k16.row.col.f32.bf16.bf16.f32 " \
        "{%0,%1,%2,%3},{%4,%5,%6,%7},{%8,%9},{%0,%1,%2,%3};" \
        : "+f"((d)[0]), "+f"((d)[1]), "+f"((d)[2]), "+f"((d)[3]) \
        : "r"(a0), "r"(a1), "r"(a2), "r"(a3), "r"(b0), "r"(b1))

__device__ __forceinline__ float sinbias(int i, int n) {
    int j2 = n & ~1;
    float ang = (float)i * expf(-(float)j2 * (9.210340371976184f / 1024.f));
    return (n & 1) ? cosf(ang) : sinf(ang);
}

// ================ segment average ================
__global__ void avg_k(const float* __restrict__ x, float* __restrict__ altx) {
    int idx = blockIdx.x * 256 + threadIdx.x;
    int i = idx >> 11;
    int m = idx & 2047;
    int c1 = m >> 5;
    int c2 = m & 31;
    const float4* p = (const float4*)(x + ((c2 << 6) + c1) * 2048 + (i << 6));
    float s = 0.f;
#pragma unroll
    for (int t = 0; t < 16; t++) { float4 v = p[t]; s += v.x + v.y + v.z + v.w; }
    altx[idx] = s * (1.f / 64.f);
}

// ================ bf16-split tensor-core GEMM (legacy mma.sync) ================
// D[128 rows (W) x 32 tokens] per CTA.  W [N][K], X [32][K] fp32 row-major.
// Partials: P[split][token][row_global].
// smem buffer layout (20480 B): Ah[128x32 bf16 @64B pitch]=8192, Al=8192,
//                               Bh[32x32 bf16 @64B pitch]=2048, Bl=2048.
#define KC 32
#define BUFSZ 20480

__global__ __launch_bounds__(256, 2) void gemm_mma(
    const float* __restrict__ X, const float* __restrict__ W,
    float* __restrict__ P, int N, int K, int kc)
{
    __shared__ __align__(16) char sm[2][BUFSZ];

    int tid = threadIdx.x;
    int wid = tid >> 5, lane = tid & 31;
    int warp_m = wid >> 1;            // 0..3 -> 32 rows each
    int warp_n = wid & 1;             // 0..1 -> 16 tokens each

    // global loader mapping
    int arow = tid >> 1;              // 0..127
    int aks = (tid & 1) * 16;         // float offset within 32-float chunk
    int brow = tid >> 3;              // 0..31
    int bks = (tid & 7) * 4;

    const float* Ap = W + (size_t)(blockIdx.x * 128 + arow) * K + aks;
    const float* Bp = X + (size_t)brow * K + bks;
    int k0 = blockIdx.y * kc;
    int NCH = kc / KC;

    float4 a4[4];
    float4 b4;
#pragma unroll
    for (int c = 0; c < 4; c++) a4[c] = *(const float4*)&Ap[k0 + c * 4];
    b4 = *(const float4*)&Bp[k0];

    float d[2][2][4];
#pragma unroll
    for (int mt = 0; mt < 2; mt++)
#pragma unroll
        for (int nf = 0; nf < 2; nf++)
#pragma unroll
            for (int i = 0; i < 4; i++) d[mt][nf][i] = 0.f;

    uint32_t sb = smem_u32(sm);

    // precompute ldmatrix lane offsets
    int mat = lane >> 3, rin = lane & 7;
    uint32_t a_r = (uint32_t)((mat & 1) * 8 + rin);        // + warp_m*32 + mt*16
    uint32_t a_kb = (uint32_t)((mat >> 1) * 16);           // + kk*32
    // B (non-trans): lanes 0-7 -> tokens 0-7 k0-7; 8-15 -> tokens 0-7 k8-15;
    //                16-23 -> tokens 8-15 k0-7; 24-31 -> tokens 8-15 k8-15
    uint32_t b_n = (uint32_t)(warp_n * 16 + (lane >> 4) * 8 + (lane & 7));
    uint32_t b_kb = (uint32_t)(((lane >> 3) & 1) * 16);    // + kk*32

    for (int ch = 0; ch < NCH; ch++) {
        char* bb = sm[ch & 1];
        uint32_t bufb = sb + (uint32_t)((ch & 1) * BUFSZ);

        // ---- convert & store A (32B per thread) ----
#pragma unroll
        for (int g = 0; g < 2; g++) {
            float4 u = a4[2 * g], v = a4[2 * g + 1];
            uint4 hi, lo;
            hi.x = pack_split(u.x, u.y, lo.x);
            hi.y = pack_split(u.z, u.w, lo.y);
            hi.z = pack_split(v.x, v.y, lo.z);
            hi.w = pack_split(v.z, v.w, lo.w);
            uint32_t off = (uint32_t)(arow * 64 + aks * 2 + g * 16);
            uint32_t sw = SWA(off);
            *(uint4*)(bb + sw) = hi;
            *(uint4*)(bb + 8192 + sw) = lo;
        }
        // ---- convert & store B (8B per thread) ----
        {
            uint2 hi, lo;
            hi.x = pack_split(b4.x, b4.y, lo.x);
            hi.y = pack_split(b4.z, b4.w, lo.y);
            uint32_t off = (uint32_t)(brow * 64 + bks * 2);
            uint32_t sw = SWA(off);
            *(uint2*)(bb + 16384 + sw) = hi;
            *(uint2*)(bb + 18432 + sw) = lo;
        }

        // prefetch next chunk while smem fills
        if (ch + 1 < NCH) {
            int k = k0 + (ch + 1) * KC;
#pragma unroll
            for (int c = 0; c < 4; c++) a4[c] = *(const float4*)&Ap[k + c * 4];
            b4 = *(const float4*)&Bp[k];
        }
        __syncthreads();

        // ---- compute: 2 k16 steps ----
#pragma unroll
        for (int kk = 0; kk < 2; kk++) {
            uint32_t ah[2][4], al[2][4];
#pragma unroll
            for (int mt = 0; mt < 2; mt++) {
                uint32_t off = SWA((uint32_t)((warp_m * 32 + mt * 16 + a_r) * 64)
                                   + (uint32_t)(kk * 32) + a_kb);
                LDSM4(ah[mt][0], ah[mt][1], ah[mt][2], ah[mt][3], bufb + off);
                LDSM4(al[mt][0], al[mt][1], al[mt][2], al[mt][3], bufb + 8192 + off);
            }
            uint32_t bh[4], bl[4];
            {
                uint32_t off = SWA(b_n * 64 + (uint32_t)(kk * 32) + b_kb);
                LDSM4(bh[0], bh[1], bh[2], bh[3], bufb + 16384 + off);
                LDSM4(bl[0], bl[1], bl[2], bl[3], bufb + 18432 + off);
            }
#pragma unroll
            for (int mt = 0; mt < 2; mt++) {
#pragma unroll
                for (int nf = 0; nf < 2; nf++) {
                    MMA16816(d[mt][nf], ah[mt][0], ah[mt][1], ah[mt][2], ah[mt][3],
                             bh[nf * 2], bh[nf * 2 + 1]);
                    MMA16816(d[mt][nf], ah[mt][0], ah[mt][1], ah[mt][2], ah[mt][3],
                             bl[nf * 2], bl[nf * 2 + 1]);
                    MMA16816(d[mt][nf], al[mt][0], al[mt][1], al[mt][2], al[mt][3],
                             bh[nf * 2], bh[nf * 2 + 1]);
                }
            }
        }
        __syncthreads();
    }

    // ---- epilogue: transpose via smem, store token-major partials ----
    float* ep = (float*)sm;   // 32 x 132 floats = 16896 B
#pragma unroll
    for (int mt = 0; mt < 2; mt++)
#pragma unroll
        for (int nf = 0; nf < 2; nf++)
#pragma unroll
            for (int i = 0; i < 4; i++) {
                int m = warp_m * 32 + mt * 16 + (lane >> 2) + ((i >> 1) << 3);
                int tok = warp_n * 16 + nf * 8 + (lane & 3) * 2 + (i & 1);
                ep[tok * 132 + m] = d[mt][nf][i];
            }
    __syncthreads();
    {
        size_t pb = (size_t)blockIdx.y * 32 * N + blockIdx.x * 128;
        for (int e = tid; e < 4096; e += 256) {
            int tok = e >> 7, m = e & 127;
            P[pb + (size_t)tok * N + m] = ep[tok * 132 + m];
        }
    }
}

// ================ LN stat helper ================
__device__ __forceinline__ void ln_stats(float sum, float sq, float* red, int tid,
                                         float& mu, float& rstd) {
    int w = tid >> 5, lane = tid & 31;
#pragma unroll
    for (int off = 16; off; off >>= 1) {
        sum += __shfl_xor_sync(0xffffffffu, sum, off);
        sq  += __shfl_xor_sync(0xffffffffu, sq, off);
    }
    if (lane == 0) { red[w] = sum; red[32 + w] = sq; }
    __syncthreads();
    if (tid == 0) {
        float a = 0.f, b = 0.f;
        for (int k = 0; k < 8; k++) { a += red[k]; b += red[32 + k]; }
        red[60] = a; red[61] = b;
    }
    __syncthreads();
    mu = red[60] * (1.f / 2048.f);
    float var = red[61] * (1.f / 2048.f) - mu * mu;
    rstd = rsqrtf(var + EPS);
}

// ================ fused epilogues (grid = 32 tokens) ================
__global__ void postA_k(const float* __restrict__ P, float* __restrict__ s,
                        float* __restrict__ y, const float* __restrict__ g,
                        const float* __restrict__ bt, int ks)
{
    __shared__ float red[64];
    int i = blockIdx.x, tid = threadIdx.x;
    float v[8]; float sum = 0.f, sq = 0.f;
#pragma unroll
    for (int j = 0; j < 8; j++) {
        int n = tid + j * 256;
        float a = 0.f;
        for (int sp = 0; sp < ks; sp++) a += P[(size_t)sp * 65536 + i * 2048 + n];
        a += sinbias(i, n);
        v[j] = a; s[i * 2048 + n] = a; sum += a; sq += a * a;
    }
    float mu, rstd;
    ln_stats(sum, sq, red, tid, mu, rstd);
#pragma unroll
    for (int j = 0; j < 8; j++) {
        int n = tid + j * 256;
        y[i * 2048 + n] = (v[j] - mu) * rstd * g[n] + bt[n];
    }
}

__global__ void postB_k(const float* __restrict__ P, float* __restrict__ s,
                        const float* __restrict__ g, const float* __restrict__ bt, int ks)
{
    __shared__ float red[64];
    int i = blockIdx.x, tid = threadIdx.x;
    float v[8]; float sum = 0.f, sq = 0.f;
#pragma unroll
    for (int j = 0; j < 8; j++) {
        int n = tid + j * 256;
        float a = 0.f;
        for (int sp = 0; sp < ks; sp++) a += P[(size_t)sp * 65536 + i * 2048 + n];
        a += s[i * 2048 + n];
        v[j] = a; sum += a; sq += a * a;
    }
    float mu, rstd;
    ln_stats(sum, sq, red, tid, mu, rstd);
#pragma unroll
    for (int j = 0; j < 8; j++) {
        int n = tid + j * 256;
        s[i * 2048 + n] = (v[j] - mu) * rstd * g[n] + bt[n] + v[j];
    }
}

__global__ void postC_k(const float* __restrict__ P, float* __restrict__ h,
                        const float* __restrict__ bias, int ks)
{
    int i = blockIdx.x, tid = threadIdx.x;
#pragma unroll
    for (int j = 0; j < 32; j++) {
        int n = tid + j * 256;
        float a = 0.f;
        for (int sp = 0; sp < ks; sp++) a += P[(size_t)sp * 262144 + i * 8192 + n];
        a += bias[n];
        h[i * 8192 + n] = 0.5f * a * (1.f + erff(a * 0.70710678118654752f));
    }
}

__global__ void postD_k(const float* __restrict__ P, float* __restrict__ s,
                        float* __restrict__ y, const float* __restrict__ bias,
                        const float* __restrict__ g, const float* __restrict__ bt,
                        float* __restrict__ out, int last, int ks)
{
    __shared__ float red[64];
    int i = blockIdx.x, tid = threadIdx.x;
    float v[8]; float sum = 0.f, sq = 0.f;
#pragma unroll
    for (int j = 0; j < 8; j++) {
        int n = tid + j * 256;
        float a = 0.f;
        for (int sp = 0; sp < ks; sp++) a += P[(size_t)sp * 65536 + i * 2048 + n];
        a += bias[n];
        v[j] = a; sum += a; sq += a * a;
    }
    if (last) {
#pragma unroll
        for (int j = 0; j < 8; j++) out[i * 2048 + tid + j * 256] = v[j];
        return;
    }
    float mu, rstd;
    ln_stats(sum, sq, red, tid, mu, rstd);
#pragma unroll
    for (int j = 0; j < 8; j++) {
        int n = tid + j * 256;
        s[i * 2048 + n] = v[j];
        y[i * 2048 + n] = (v[j] - mu) * rstd * g[n] + bt[n];
    }
}

// ================ scalar attention + cumsum (fused qkv split-K sum) ================
__global__ void attn_k(const float* __restrict__ P, float* __restrict__ imv, int ks) {
    const size_t ST = (size_t)32 * 6144;
    int h = blockIdx.x;
    int tid = threadIdx.x;
    int w = tid >> 5, lane = tid & 31;
    __shared__ float rsa[32];

#pragma unroll
    for (int ii = 0; ii < 8; ii++) {
        int i = w * 8 + ii;
        size_t qb = (size_t)i * 6144 + h * 128 + lane * 4;
        float4 qa = make_float4(0.f, 0.f, 0.f, 0.f), ka = make_float4(0.f, 0.f, 0.f, 0.f);
        for (int sp = 0; sp < ks; sp++) {
            float4 q = *(const float4*)&P[sp * ST + qb];
            float4 k = *(const float4*)&P[sp * ST + qb + 2048];
            qa.x += q.x; qa.y += q.y; qa.z += q.z; qa.w += q.w;
            ka.x += k.x; ka.y += k.y; ka.z += k.z; ka.w += k.w;
        }
        float p = qa.x * ka.x + qa.y * ka.y + qa.z * ka.z + qa.w * ka.w;
#pragma unroll
        for (int off = 16; off; off >>= 1) p += __shfl_xor_sync(0xffffffffu, p, off);
        if (lane == 0) rsa[i] = p * 0.08838834764831845f;
    }
    __syncthreads();

    int d = tid;
    float run = 0.f;
#pragma unroll
    for (int i = 0; i < 32; i++) {
        size_t vb = (size_t)i * 6144 + 4096 + h * 128 + d;
        float vv = 0.f;
        for (int sp = 0; sp < ks; sp++) vv += P[sp * ST + vb];
        run += rsa[i] * vv;
        imv[i * 2048 + h * 128 + d] = run;
    }
}

// ================ launch ================
extern "C" void kernel_launch(void* const* d_in, const int* in_sizes, int n_in,
                              void* d_out, int out_size)
{
    const float* x      = (const float*)d_in[0];
    const float* weight = (const float*)d_in[1];
    const float* Wqkv   = (const float*)d_in[2];
    const float* Wo     = (const float*)d_in[3];
    const float* ln1_g  = (const float*)d_in[4];
    const float* ln1_b  = (const float*)d_in[5];
    const float* ln2_g  = (const float*)d_in[6];
    const float* ln2_b  = (const float*)d_in[7];
    const float* fc1_w  = (const float*)d_in[8];
    const float* fc1_b  = (const float*)d_in[9];
    const float* fc2_w  = (const float*)d_in[10];
    const float* fc2_b  = (const float*)d_in[11];
    float* out = (float*)d_out;

    float *p_altx, *p_s, *p_y, *p_imv, *p_h, *p_part;
    cudaGetSymbolAddress((void**)&p_altx, g_altx);
    cudaGetSymbolAddress((void**)&p_s,    g_s);
    cudaGetSymbolAddress((void**)&p_y,    g_y);
    cudaGetSymbolAddress((void**)&p_imv,  g_imv);
    cudaGetSymbolAddress((void**)&p_h,    g_h);
    cudaGetSymbolAddress((void**)&p_part, g_part);

    avg_k<<<256, 256>>>(x, p_altx);

    // s = weight @ altx^T + sinbias ; y = LN1(s)     (N=2048, K=2048, ks=8)
    gemm_mma<<<dim3(16, 8), 256>>>(p_altx, weight, p_part, MD, MD, 256);
    postA_k<<<32, 256>>>(p_part, p_s, p_y, ln1_g, ln1_b, 8);

    for (int a = 0; a < 3; a++) {
        // qkv partials   (N=6144, K=2048, ks=8)
        gemm_mma<<<dim3(48, 8), 256>>>(p_y, Wqkv + (size_t)a * NQKV * MD,
                                       p_part, NQKV, MD, 256);
        attn_k<<<16, 128>>>(p_part, p_imv, 8);

        // s' = Wo@imv + s ; s = LN2(s')+s'   (ks=8)
        gemm_mma<<<dim3(16, 8), 256>>>(p_imv, Wo + (size_t)a * MD * MD,
                                       p_part, MD, MD, 256);
        postB_k<<<32, 256>>>(p_part, p_s, ln2_g, ln2_b, 8);

        // h = gelu(fc1@s + b1)   (N=8192, K=2048, ks=4)
        gemm_mma<<<dim3(64, 4), 256>>>(p_s, fc1_w, p_part, NFF, MD, 512);
        postC_k<<<32, 256>>>(p_part, p_h, fc1_b, 4);

        // s = fc2@h + b2   (N=2048, K=8192, ks=8)
        gemm_mma<<<dim3(16, 8), 256>>>(p_h, fc2_w, p_part, MD, NFF, 1024);
        postD_k<<<32, 256>>>(p_part, p_s, p_y, fc2_b, ln1_g, ln1_b, out, a == 2, 8);
    }
}

// round 9
// speedup vs baseline: 1.0391x; 1.0391x over previous
#include <cuda_runtime.h>
#include <cuda_bf16.h>
#include <math.h>
#include <stdint.h>

// ---------------- dims ----------------
#define MD 2048
#define NQKV 6144
#define NFF 8192
#define EPS 1e-5f

// ---------------- scratch ----------------
__device__ float g_altx[32 * MD];
__device__ float g_s[32 * MD];
__device__ float g_y[32 * MD];
__device__ float g_imv[32 * MD];
__device__ float g_h[32 * NFF];
__device__ float g_part[2097152];   // 8 MB: max ks*32*N partials (fc1: 8*32*8192)

// ---------------- helpers ----------------
#define SWA(o) ((o) ^ ((((o) >> 7) & 3u) << 4))

__device__ __forceinline__ uint32_t smem_u32(const void* p) {
    uint32_t a;
    asm("{ .reg .u64 t; cvta.to.shared.u64 t, %1; cvt.u32.u64 %0, t; }" : "=r"(a) : "l"(p));
    return a;
}

// cheap split: hi = truncate-to-bf16 (top 16 bits), lo = bf16(f - hi) (truncated).
// per 2 elements: 2 AND + 2 FADD + 2 PRMT.
__device__ __forceinline__ void pack2(float f0, float f1, uint32_t& hi, uint32_t& lo) {
    uint32_t u0 = __float_as_uint(f0), u1 = __float_as_uint(f1);
    float l0 = f0 - __uint_as_float(u0 & 0xffff0000u);
    float l1 = f1 - __uint_as_float(u1 & 0xffff0000u);
    hi = __byte_perm(u0, u1, 0x7632);
    lo = __byte_perm(__float_as_uint(l0), __float_as_uint(l1), 0x7632);
}

#define LDSM4(r0, r1, r2, r3, a) \
    asm volatile("ldmatrix.sync.aligned.m8n8.x4.shared.b16 {%0,%1,%2,%3},[%4];" \
        : "=r"(r0), "=r"(r1), "=r"(r2), "=r"(r3) : "r"(a))

#define MMA16816(d, a0, a1, a2, a3, b0, b1) \
    asm volatile("mma.sync.aligned.m16n8k16.row.col.f32.bf16.bf16.f32 " \
        "{%0,%1,%2,%3},{%4,%5,%6,%7},{%8,%9},{%0,%1,%2,%3};" \
        : "+f"((d)[0]), "+f"((d)[1]), "+f"((d)[2]), "+f"((d)[3]) \
        : "r"(a0), "r"(a1), "r"(a2), "r"(a3), "r"(b0), "r"(b1))

__device__ __forceinline__ float sinbias(int i, int n) {
    int j2 = n & ~1;
    float ang = (float)i * expf(-(float)j2 * (9.210340371976184f / 1024.f));
    return (n & 1) ? cosf(ang) : sinf(ang);
}

// ================ segment average ================
__global__ void avg_k(const float* __restrict__ x, float* __restrict__ altx) {
    int idx = blockIdx.x * 256 + threadIdx.x;
    int i = idx >> 11;
    int m = idx & 2047;
    int c1 = m >> 5;
    int c2 = m & 31;
    const float4* p = (const float4*)(x + ((c2 << 6) + c1) * 2048 + (i << 6));
    float s = 0.f;
#pragma unroll
    for (int t = 0; t < 16; t++) { float4 v = p[t]; s += v.x + v.y + v.z + v.w; }
    altx[idx] = s * (1.f / 64.f);
}

// ================ bf16-split tensor-core GEMM (legacy mma.sync) ================
// D[128 W-rows x 32 tokens] per CTA.  W [N][K], X [32][K] fp32 row-major.
// Partials: P[split][token][row_global].
#define KC 32
#define BUFSZ 20480

__global__ __launch_bounds__(256, 3) void gemm_mma(
    const float* __restrict__ X, const float* __restrict__ W,
    float* __restrict__ P, int N, int K, int kc)
{
    __shared__ __align__(16) char sm[2][BUFSZ];

    int tid = threadIdx.x;
    int wid = tid >> 5, lane = tid & 31;
    int warp_m = wid >> 1;            // 0..3 -> 32 rows each
    int warp_n = wid & 1;             // 0..1 -> 16 tokens each

    int arow = tid >> 1;              // 0..127
    int aks = (tid & 1) * 16;
    int brow = tid >> 3;              // 0..31
    int bks = (tid & 7) * 4;

    const float* Ap = W + (size_t)(blockIdx.x * 128 + arow) * K + aks;
    const float* Bp = X + (size_t)brow * K + bks;
    int k0 = blockIdx.y * kc;
    int NCH = kc / KC;

    float4 a4[4];
    float4 b4;
#pragma unroll
    for (int c = 0; c < 4; c++) a4[c] = *(const float4*)&Ap[k0 + c * 4];
    b4 = *(const float4*)&Bp[k0];

    float d[2][2][4];
#pragma unroll
    for (int mt = 0; mt < 2; mt++)
#pragma unroll
        for (int nf = 0; nf < 2; nf++)
#pragma unroll
            for (int i = 0; i < 4; i++) d[mt][nf][i] = 0.f;

    uint32_t sb = smem_u32(sm);

    int mat = lane >> 3, rin = lane & 7;
    uint32_t a_r = (uint32_t)((mat & 1) * 8 + rin);
    uint32_t a_kb = (uint32_t)((mat >> 1) * 16);
    uint32_t b_n = (uint32_t)(warp_n * 16 + (lane >> 4) * 8 + (lane & 7));
    uint32_t b_kb = (uint32_t)(((lane >> 3) & 1) * 16);

    for (int ch = 0; ch < NCH; ch++) {
        char* bb = sm[ch & 1];
        uint32_t bufb = sb + (uint32_t)((ch & 1) * BUFSZ);

        // ---- convert & store A ----
#pragma unroll
        for (int g = 0; g < 2; g++) {
            float4 u = a4[2 * g], v = a4[2 * g + 1];
            uint4 hi, lo;
            pack2(u.x, u.y, hi.x, lo.x);
            pack2(u.z, u.w, hi.y, lo.y);
            pack2(v.x, v.y, hi.z, lo.z);
            pack2(v.z, v.w, hi.w, lo.w);
            uint32_t off = (uint32_t)(arow * 64 + aks * 2 + g * 16);
            uint32_t sw = SWA(off);
            *(uint4*)(bb + sw) = hi;
            *(uint4*)(bb + 8192 + sw) = lo;
        }
        // ---- convert & store B ----
        {
            uint2 hi, lo;
            pack2(b4.x, b4.y, hi.x, lo.x);
            pack2(b4.z, b4.w, hi.y, lo.y);
            uint32_t off = (uint32_t)(brow * 64 + bks * 2);
            uint32_t sw = SWA(off);
            *(uint2*)(bb + 16384 + sw) = hi;
            *(uint2*)(bb + 18432 + sw) = lo;
        }

        if (ch + 1 < NCH) {
            int k = k0 + (ch + 1) * KC;
#pragma unroll
            for (int c = 0; c < 4; c++) a4[c] = *(const float4*)&Ap[k + c * 4];
            b4 = *(const float4*)&Bp[k];
        }
        __syncthreads();

        // ---- compute: 2 k16 steps ----
#pragma unroll
        for (int kk = 0; kk < 2; kk++) {
            uint32_t ah[2][4], al[2][4];
#pragma unroll
            for (int mt = 0; mt < 2; mt++) {
                uint32_t off = SWA((uint32_t)((warp_m * 32 + mt * 16 + a_r) * 64)
                                   + (uint32_t)(kk * 32) + a_kb);
                LDSM4(ah[mt][0], ah[mt][1], ah[mt][2], ah[mt][3], bufb + off);
                LDSM4(al[mt][0], al[mt][1], al[mt][2], al[mt][3], bufb + 8192 + off);
            }
            uint32_t bh[4], bl[4];
            {
                uint32_t off = SWA(b_n * 64 + (uint32_t)(kk * 32) + b_kb);
                LDSM4(bh[0], bh[1], bh[2], bh[3], bufb + 16384 + off);
                LDSM4(bl[0], bl[1], bl[2], bl[3], bufb + 18432 + off);
            }
#pragma unroll
            for (int mt = 0; mt < 2; mt++) {
#pragma unroll
                for (int nf = 0; nf < 2; nf++) {
                    MMA16816(d[mt][nf], ah[mt][0], ah[mt][1], ah[mt][2], ah[mt][3],
                             bh[nf * 2], bh[nf * 2 + 1]);
                    MMA16816(d[mt][nf], ah[mt][0], ah[mt][1], ah[mt][2], ah[mt][3],
                             bl[nf * 2], bl[nf * 2 + 1]);
                    MMA16816(d[mt][nf], al[mt][0], al[mt][1], al[mt][2], al[mt][3],
                             bh[nf * 2], bh[nf * 2 + 1]);
                }
            }
        }
        __syncthreads();
    }

    // ---- epilogue: transpose via smem, store token-major partials ----
    float* ep = (float*)sm;   // 32 x 132 floats
#pragma unroll
    for (int mt = 0; mt < 2; mt++)
#pragma unroll
        for (int nf = 0; nf < 2; nf++)
#pragma unroll
            for (int i = 0; i < 4; i++) {
                int m = warp_m * 32 + mt * 16 + (lane >> 2) + ((i >> 1) << 3);
                int tok = warp_n * 16 + nf * 8 + (lane & 3) * 2 + (i & 1);
                ep[tok * 132 + m] = d[mt][nf][i];
            }
    __syncthreads();
    {
        size_t pb = (size_t)blockIdx.y * 32 * N + blockIdx.x * 128;
        for (int e = tid; e < 4096; e += 256) {
            int tok = e >> 7, m = e & 127;
            P[pb + (size_t)tok * N + m] = ep[tok * 132 + m];
        }
    }
}

// ================ LN stat helper ================
__device__ __forceinline__ void ln_stats(float sum, float sq, float* red, int tid,
                                         float& mu, float& rstd) {
    int w = tid >> 5, lane = tid & 31;
#pragma unroll
    for (int off = 16; off; off >>= 1) {
        sum += __shfl_xor_sync(0xffffffffu, sum, off);
        sq  += __shfl_xor_sync(0xffffffffu, sq, off);
    }
    if (lane == 0) { red[w] = sum; red[32 + w] = sq; }
    __syncthreads();
    if (tid == 0) {
        float a = 0.f, b = 0.f;
        for (int k = 0; k < 8; k++) { a += red[k]; b += red[32 + k]; }
        red[60] = a; red[61] = b;
    }
    __syncthreads();
    mu = red[60] * (1.f / 2048.f);
    float var = red[61] * (1.f / 2048.f) - mu * mu;
    rstd = rsqrtf(var + EPS);
}

// ================ fused epilogues (grid = 32 tokens) ================
__global__ void postA_k(const float* __restrict__ P, float* __restrict__ s,
                        float* __restrict__ y, const float* __restrict__ g,
                        const float* __restrict__ bt, int ks)
{
    __shared__ float red[64];
    int i = blockIdx.x, tid = threadIdx.x;
    float v[8]; float sum = 0.f, sq = 0.f;
#pragma unroll
    for (int j = 0; j < 8; j++) {
        int n = tid + j * 256;
        float a = 0.f;
        for (int sp = 0; sp < ks; sp++) a += P[(size_t)sp * 65536 + i * 2048 + n];
        a += sinbias(i, n);
        v[j] = a; s[i * 2048 + n] = a; sum += a; sq += a * a;
    }
    float mu, rstd;
    ln_stats(sum, sq, red, tid, mu, rstd);
#pragma unroll
    for (int j = 0; j < 8; j++) {
        int n = tid + j * 256;
        y[i * 2048 + n] = (v[j] - mu) * rstd * g[n] + bt[n];
    }
}

__global__ void postB_k(const float* __restrict__ P, float* __restrict__ s,
                        const float* __restrict__ g, const float* __restrict__ bt, int ks)
{
    __shared__ float red[64];
    int i = blockIdx.x, tid = threadIdx.x;
    float v[8]; float sum = 0.f, sq = 0.f;
#pragma unroll
    for (int j = 0; j < 8; j++) {
        int n = tid + j * 256;
        float a = 0.f;
        for (int sp = 0; sp < ks; sp++) a += P[(size_t)sp * 65536 + i * 2048 + n];
        a += s[i * 2048 + n];
        v[j] = a; sum += a; sq += a * a;
    }
    float mu, rstd;
    ln_stats(sum, sq, red, tid, mu, rstd);
#pragma unroll
    for (int j = 0; j < 8; j++) {
        int n = tid + j * 256;
        s[i * 2048 + n] = (v[j] - mu) * rstd * g[n] + bt[n] + v[j];
    }
}

__global__ void postC_k(const float* __restrict__ P, float* __restrict__ h,
                        const float* __restrict__ bias, int ks)
{
    int i = blockIdx.x, tid = threadIdx.x;
#pragma unroll
    for (int j = 0; j < 32; j++) {
        int n = tid + j * 256;
        float a = 0.f;
        for (int sp = 0; sp < ks; sp++) a += P[(size_t)sp * 262144 + i * 8192 + n];
        a += bias[n];
        h[i * 8192 + n] = 0.5f * a * (1.f + erff(a * 0.70710678118654752f));
    }
}

__global__ void postD_k(const float* __restrict__ P, float* __restrict__ s,
                        float* __restrict__ y, const float* __restrict__ bias,
                        const float* __restrict__ g, const float* __restrict__ bt,
                        float* __restrict__ out, int last, int ks)
{
    __shared__ float red[64];
    int i = blockIdx.x, tid = threadIdx.x;
    float v[8]; float sum = 0.f, sq = 0.f;
#pragma unroll
    for (int j = 0; j < 8; j++) {
        int n = tid + j * 256;
        float a = 0.f;
        for (int sp = 0; sp < ks; sp++) a += P[(size_t)sp * 65536 + i * 2048 + n];
        a += bias[n];
        v[j] = a; sum += a; sq += a * a;
    }
    if (last) {
#pragma unroll
        for (int j = 0; j < 8; j++) out[i * 2048 + tid + j * 256] = v[j];
        return;
    }
    float mu, rstd;
    ln_stats(sum, sq, red, tid, mu, rstd);
#pragma unroll
    for (int j = 0; j < 8; j++) {
        int n = tid + j * 256;
        s[i * 2048 + n] = v[j];
        y[i * 2048 + n] = (v[j] - mu) * rstd * g[n] + bt[n];
    }
}

// ================ scalar attention + cumsum (fused qkv split-K sum) ================
__global__ void attn_k(const float* __restrict__ P, float* __restrict__ imv, int ks) {
    const size_t ST = (size_t)32 * 6144;
    int h = blockIdx.x;
    int tid = threadIdx.x;
    int w = tid >> 5, lane = tid & 31;
    __shared__ float rsa[32];

#pragma unroll
    for (int ii = 0; ii < 8; ii++) {
        int i = w * 8 + ii;
        size_t qb = (size_t)i * 6144 + h * 128 + lane * 4;
        float4 qa = make_float4(0.f, 0.f, 0.f, 0.f), ka = make_float4(0.f, 0.f, 0.f, 0.f);
        for (int sp = 0; sp < ks; sp++) {
            float4 q = *(const float4*)&P[sp * ST + qb];
            float4 k = *(const float4*)&P[sp * ST + qb + 2048];
            qa.x += q.x; qa.y += q.y; qa.z += q.z; qa.w += q.w;
            ka.x += k.x; ka.y += k.y; ka.z += k.z; ka.w += k.w;
        }
        float p = qa.x * ka.x + qa.y * ka.y + qa.z * ka.z + qa.w * ka.w;
#pragma unroll
        for (int off = 16; off; off >>= 1) p += __shfl_xor_sync(0xffffffffu, p, off);
        if (lane == 0) rsa[i] = p * 0.08838834764831845f;
    }
    __syncthreads();

    int d = tid;
    float run = 0.f;
#pragma unroll
    for (int i = 0; i < 32; i++) {
        size_t vb = (size_t)i * 6144 + 4096 + h * 128 + d;
        float vv = 0.f;
        for (int sp = 0; sp < ks; sp++) vv += P[sp * ST + vb];
        run += rsa[i] * vv;
        imv[i * 2048 + h * 128 + d] = run;
    }
}

// ================ launch ================
extern "C" void kernel_launch(void* const* d_in, const int* in_sizes, int n_in,
                              void* d_out, int out_size)
{
    const float* x      = (const float*)d_in[0];
    const float* weight = (const float*)d_in[1];
    const float* Wqkv   = (const float*)d_in[2];
    const float* Wo     = (const float*)d_in[3];
    const float* ln1_g  = (const float*)d_in[4];
    const float* ln1_b  = (const float*)d_in[5];
    const float* ln2_g  = (const float*)d_in[6];
    const float* ln2_b  = (const float*)d_in[7];
    const float* fc1_w  = (const float*)d_in[8];
    const float* fc1_b  = (const float*)d_in[9];
    const float* fc2_w  = (const float*)d_in[10];
    const float* fc2_b  = (const float*)d_in[11];
    float* out = (float*)d_out;

    float *p_altx, *p_s, *p_y, *p_imv, *p_h, *p_part;
    cudaGetSymbolAddress((void**)&p_altx, g_altx);
    cudaGetSymbolAddress((void**)&p_s,    g_s);
    cudaGetSymbolAddress((void**)&p_y,    g_y);
    cudaGetSymbolAddress((void**)&p_imv,  g_imv);
    cudaGetSymbolAddress((void**)&p_h,    g_h);
    cudaGetSymbolAddress((void**)&p_part, g_part);

    avg_k<<<256, 256>>>(x, p_altx);

    // s = weight @ altx^T + sinbias ; y = LN1(s)   (N=2048, K=2048, ks=16)
    gemm_mma<<<dim3(16, 16), 256>>>(p_altx, weight, p_part, MD, MD, 128);
    postA_k<<<32, 256>>>(p_part, p_s, p_y, ln1_g, ln1_b, 16);

    for (int a = 0; a < 3; a++) {
        // qkv partials   (N=6144, K=2048, ks=8)
        gemm_mma<<<dim3(48, 8), 256>>>(p_y, Wqkv + (size_t)a * NQKV * MD,
                                       p_part, NQKV, MD, 256);
        attn_k<<<16, 128>>>(p_part, p_imv, 8);

        // s' = Wo@imv + s ; s = LN2(s')+s'   (ks=16)
        gemm_mma<<<dim3(16, 16), 256>>>(p_imv, Wo + (size_t)a * MD * MD,
                                        p_part, MD, MD, 128);
        postB_k<<<32, 256>>>(p_part, p_s, ln2_g, ln2_b, 16);

        // h = gelu(fc1@s + b1)   (N=8192, K=2048, ks=8)
        gemm_mma<<<dim3(64, 8), 256>>>(p_s, fc1_w, p_part, NFF, MD, 256);
        postC_k<<<32, 256>>>(p_part, p_h, fc1_b, 8);

        // s = fc2@h + b2   (N=2048, K=8192, ks=16)
        gemm_mma<<<dim3(16, 16), 256>>>(p_h, fc2_w, p_part, MD, NFF, 512);
        postD_k<<<32, 256>>>(p_part, p_s, p_y, fc2_b, ln1_g, ln1_b, out, a == 2, 16);
    }
}

// round 10
// speedup vs baseline: 1.3373x; 1.2870x over previous
#include <cuda_runtime.h>
#include <cuda_bf16.h>
#include <math.h>
#include <stdint.h>

// ---------------- dims ----------------
#define MD 2048
#define NQKV 6144
#define NFF 8192
#define EPS 1e-5f

// ---------------- scratch ----------------
__device__ float g_altx[32 * MD];
__device__ float g_s[32 * MD];
__device__ float g_y[32 * MD];
__device__ float g_imv[32 * MD];
__device__ float g_h[32 * NFF];
__device__ float g_part[2097152];   // 8 MB partials

// ---------------- helpers ----------------
#define SWA(o) ((o) ^ ((((o) >> 7) & 3u) << 4))

__device__ __forceinline__ uint32_t smem_u32(const void* p) {
    uint32_t a;
    asm("{ .reg .u64 t; cvta.to.shared.u64 t, %1; cvt.u32.u64 %0, t; }" : "=r"(a) : "l"(p));
    return a;
}

// cheap split: hi = truncate-to-bf16 (top 16 bits), lo = bf16(f - hi) (truncated)
__device__ __forceinline__ void pack2(float f0, float f1, uint32_t& hi, uint32_t& lo) {
    uint32_t u0 = __float_as_uint(f0), u1 = __float_as_uint(f1);
    float l0 = f0 - __uint_as_float(u0 & 0xffff0000u);
    float l1 = f1 - __uint_as_float(u1 & 0xffff0000u);
    hi = __byte_perm(u0, u1, 0x7632);
    lo = __byte_perm(__float_as_uint(l0), __float_as_uint(l1), 0x7632);
}

#define LDSM4(r0, r1, r2, r3, a) \
    asm volatile("ldmatrix.sync.aligned.m8n8.x4.shared.b16 {%0,%1,%2,%3},[%4];" \
        : "=r"(r0), "=r"(r1), "=r"(r2), "=r"(r3) : "r"(a))

#define MMA16816(d, a0, a1, a2, a3, b0, b1) \
    asm volatile("mma.sync.aligned.m16n8k16.row.col.f32.bf16.bf16.f32 " \
        "{%0,%1,%2,%3},{%4,%5,%6,%7},{%8,%9},{%0,%1,%2,%3};" \
        : "+f"((d)[0]), "+f"((d)[1]), "+f"((d)[2]), "+f"((d)[3]) \
        : "r"(a0), "r"(a1), "r"(a2), "r"(a3), "r"(b0), "r"(b1))

__device__ __forceinline__ float sinbias(int i, int n) {
    int j2 = n & ~1;
    float ang = (float)i * expf(-(float)j2 * (9.210340371976184f / 1024.f));
    return (n & 1) ? cosf(ang) : sinf(ang);
}

// ================ segment average ================
__global__ void avg_k(const float* __restrict__ x, float* __restrict__ altx) {
    int idx = blockIdx.x * 256 + threadIdx.x;
    int i = idx >> 11;
    int m = idx & 2047;
    int c1 = m >> 5;
    int c2 = m & 31;
    const float4* p = (const float4*)(x + ((c2 << 6) + c1) * 2048 + (i << 6));
    float s = 0.f;
#pragma unroll
    for (int t = 0; t < 16; t++) { float4 v = p[t]; s += v.x + v.y + v.z + v.w; }
    altx[idx] = s * (1.f / 64.f);
}

// ================ bf16-split GEMM: A direct-to-register, 256 rows/CTA ================
// D[256 W-rows x 32 tokens] per CTA; warp w owns rows [w*32, w*32+32) x all 32 tokens.
// W [N][K], X [32][K] fp32 row-major. Partials P[split][token][row_global].
__global__ __launch_bounds__(256, 2) void gemm_mma(
    const float* __restrict__ X, const float* __restrict__ W,
    float* __restrict__ P, int N, int K, int kc)
{
    __shared__ __align__(16) union SU {
        char b[4][2048];          // B tiles: [buf*2 + hi/lo][32 tok x 64B]
        float ep[32 * 260];       // epilogue transpose
    } sm;

    int tid = threadIdx.x;
    int wid = tid >> 5, lane = tid & 31;

    // A fragment addressing: rows (lane>>2), (lane>>2)+8 ; k pair 2*(lane&3)
    int rowq = lane >> 2;
    int kpo = 2 * (lane & 3);
    const float* A0 = W + ((size_t)blockIdx.x * 256 + wid * 32 + rowq) * K + kpo;
    size_t rK8 = (size_t)8 * K;

    // B loader: thread -> token tid>>3, k-float (tid&7)*4
    int btok = tid >> 3, bkf = (tid & 7) * 4;
    const float* Bp = X + (size_t)btok * K + bkf;

    int k0 = blockIdx.y * kc;
    int NCH = kc >> 5;
    int NST = NCH * 2;

    // prologue: A regs for step 0, B vec for chunk 0
    float2 af[8];
    {
        const float* Ab = A0 + k0;
#pragma unroll
        for (int mt = 0; mt < 2; mt++) {
            const float* Am = Ab + (size_t)mt * 16 * K;
            af[mt * 4 + 0] = *(const float2*)(Am);
            af[mt * 4 + 1] = *(const float2*)(Am + rK8);
            af[mt * 4 + 2] = *(const float2*)(Am + 8);
            af[mt * 4 + 3] = *(const float2*)(Am + rK8 + 8);
        }
    }
    float4 b4 = *(const float4*)(Bp + k0);

    float d[2][4][4];
#pragma unroll
    for (int mt = 0; mt < 2; mt++)
#pragma unroll
        for (int f = 0; f < 4; f++)
#pragma unroll
            for (int i = 0; i < 4; i++) d[mt][f][i] = 0.f;

    uint32_t sb = smem_u32(&sm);
    uint32_t boff_store = SWA((uint32_t)(btok * 64 + bkf * 2));
    // B ldmatrix lane offset pieces
    uint32_t b_tokoff = (uint32_t)(((lane >> 4) * 8 + (lane & 7)) * 64);
    uint32_t b_kb = (uint32_t)(((lane >> 3) & 1) * 16);

    for (int ch = 0; ch < NCH; ch++) {
        int bi = (ch & 1) * 2;
        // store B hi/lo into smem
        {
            uint2 hi, lo;
            pack2(b4.x, b4.y, hi.x, lo.x);
            pack2(b4.z, b4.w, hi.y, lo.y);
            *(uint2*)(sm.b[bi] + boff_store) = hi;
            *(uint2*)(sm.b[bi + 1] + boff_store) = lo;
        }
        if (ch + 1 < NCH) b4 = *(const float4*)(Bp + k0 + (ch + 1) * 32);
        __syncthreads();
        uint32_t bhB = sb + (uint32_t)bi * 2048;
        uint32_t blB = bhB + 2048;

#pragma unroll
        for (int kk = 0; kk < 2; kk++) {
            int st = ch * 2 + kk;
            // convert A fp32 pairs -> bf16 hi/lo fragments
            uint32_t ah[2][4], al[2][4];
#pragma unroll
            for (int mt = 0; mt < 2; mt++)
#pragma unroll
                for (int j = 0; j < 4; j++)
                    pack2(af[mt * 4 + j].x, af[mt * 4 + j].y, ah[mt][j], al[mt][j]);
            // prefetch A for next k16 step
            if (st + 1 < NST) {
                const float* An = A0 + k0 + (st + 1) * 16;
#pragma unroll
                for (int mt = 0; mt < 2; mt++) {
                    const float* Am = An + (size_t)mt * 16 * K;
                    af[mt * 4 + 0] = *(const float2*)(Am);
                    af[mt * 4 + 1] = *(const float2*)(Am + rK8);
                    af[mt * 4 + 2] = *(const float2*)(Am + 8);
                    af[mt * 4 + 3] = *(const float2*)(Am + rK8 + 8);
                }
            }
            // B fragments: tokens 0-15 and 16-31
            uint32_t bh[8], bl[8];
#pragma unroll
            for (int g = 0; g < 2; g++) {
                uint32_t bo = SWA((uint32_t)(g * 16 * 64) + b_tokoff + b_kb + (uint32_t)(kk * 32));
                LDSM4(bh[g * 4 + 0], bh[g * 4 + 1], bh[g * 4 + 2], bh[g * 4 + 3], bhB + bo);
                LDSM4(bl[g * 4 + 0], bl[g * 4 + 1], bl[g * 4 + 2], bl[g * 4 + 3], blB + bo);
            }
            // 24 MMAs, term-major so accumulator chains are spaced by 8
#pragma unroll
            for (int mt = 0; mt < 2; mt++)
#pragma unroll
                for (int f = 0; f < 4; f++)
                    MMA16816(d[mt][f], ah[mt][0], ah[mt][1], ah[mt][2], ah[mt][3],
                             bh[f * 2], bh[f * 2 + 1]);
#pragma unroll
            for (int mt = 0; mt < 2; mt++)
#pragma unroll
                for (int f = 0; f < 4; f++)
                    MMA16816(d[mt][f], ah[mt][0], ah[mt][1], ah[mt][2], ah[mt][3],
                             bl[f * 2], bl[f * 2 + 1]);
#pragma unroll
            for (int mt = 0; mt < 2; mt++)
#pragma unroll
                for (int f = 0; f < 4; f++)
                    MMA16816(d[mt][f], al[mt][0], al[mt][1], al[mt][2], al[mt][3],
                             bh[f * 2], bh[f * 2 + 1]);
        }
    }
    __syncthreads();

    // ---- epilogue: transpose via smem (pitch 260 floats, conflict-free) ----
#pragma unroll
    for (int mt = 0; mt < 2; mt++)
#pragma unroll
        for (int f = 0; f < 4; f++)
#pragma unroll
            for (int i = 0; i < 4; i++) {
                int m = wid * 32 + mt * 16 + (lane >> 2) + ((i >> 1) << 3);
                int tok = f * 8 + (lane & 3) * 2 + (i & 1);
                sm.ep[tok * 260 + m] = d[mt][f][i];
            }
    __syncthreads();
    {
        size_t pb = (size_t)blockIdx.y * 32 * N + (size_t)blockIdx.x * 256;
        for (int e = tid; e < 8192; e += 256) {
            int tok = e >> 8, col = e & 255;
            P[pb + (size_t)tok * N + col] = sm.ep[tok * 260 + col];
        }
    }
}

// ================ LN stat helper ================
__device__ __forceinline__ void ln_stats(float sum, float sq, float* red, int tid,
                                         float& mu, float& rstd) {
    int w = tid >> 5, lane = tid & 31;
#pragma unroll
    for (int off = 16; off; off >>= 1) {
        sum += __shfl_xor_sync(0xffffffffu, sum, off);
        sq  += __shfl_xor_sync(0xffffffffu, sq, off);
    }
    if (lane == 0) { red[w] = sum; red[32 + w] = sq; }
    __syncthreads();
    if (tid == 0) {
        float a = 0.f, b = 0.f;
        for (int k = 0; k < 8; k++) { a += red[k]; b += red[32 + k]; }
        red[60] = a; red[61] = b;
    }
    __syncthreads();
    mu = red[60] * (1.f / 2048.f);
    float var = red[61] * (1.f / 2048.f) - mu * mu;
    rstd = rsqrtf(var + EPS);
}

// ================ fused epilogues ================
__global__ void postA_k(const float* __restrict__ P, float* __restrict__ s,
                        float* __restrict__ y, const float* __restrict__ g,
                        const float* __restrict__ bt, int ks)
{
    __shared__ float red[64];
    int i = blockIdx.x, tid = threadIdx.x;
    float v[8]; float sum = 0.f, sq = 0.f;
#pragma unroll
    for (int j = 0; j < 8; j++) {
        int n = tid + j * 256;
        float a = 0.f;
        for (int sp = 0; sp < ks; sp++) a += P[(size_t)sp * 65536 + i * 2048 + n];
        a += sinbias(i, n);
        v[j] = a; s[i * 2048 + n] = a; sum += a; sq += a * a;
    }
    float mu, rstd;
    ln_stats(sum, sq, red, tid, mu, rstd);
#pragma unroll
    for (int j = 0; j < 8; j++) {
        int n = tid + j * 256;
        y[i * 2048 + n] = (v[j] - mu) * rstd * g[n] + bt[n];
    }
}

__global__ void postB_k(const float* __restrict__ P, float* __restrict__ s,
                        const float* __restrict__ g, const float* __restrict__ bt, int ks)
{
    __shared__ float red[64];
    int i = blockIdx.x, tid = threadIdx.x;
    float v[8]; float sum = 0.f, sq = 0.f;
#pragma unroll
    for (int j = 0; j < 8; j++) {
        int n = tid + j * 256;
        float a = 0.f;
        for (int sp = 0; sp < ks; sp++) a += P[(size_t)sp * 65536 + i * 2048 + n];
        a += s[i * 2048 + n];
        v[j] = a; sum += a; sq += a * a;
    }
    float mu, rstd;
    ln_stats(sum, sq, red, tid, mu, rstd);
#pragma unroll
    for (int j = 0; j < 8; j++) {
        int n = tid + j * 256;
        s[i * 2048 + n] = (v[j] - mu) * rstd * g[n] + bt[n] + v[j];
    }
}

__global__ void postC_k(const float* __restrict__ P, float* __restrict__ h,
                        const float* __restrict__ bias, int ks)
{
    // grid 256 x 256 threads, 4 elems/thread over 32x8192
    int base = blockIdx.x * 1024 + threadIdx.x;
#pragma unroll
    for (int j = 0; j < 4; j++) {
        int e = base + j * 256;
        int i = e >> 13, n = e & 8191;
        float a = 0.f;
        for (int sp = 0; sp < ks; sp++) a += P[(size_t)sp * 262144 + i * 8192 + n];
        a += bias[n];
        h[e] = 0.5f * a * (1.f + erff(a * 0.70710678118654752f));
    }
}

__global__ void postD_k(const float* __restrict__ P, float* __restrict__ s,
                        float* __restrict__ y, const float* __restrict__ bias,
                        const float* __restrict__ g, const float* __restrict__ bt,
                        float* __restrict__ out, int last, int ks)
{
    __shared__ float red[64];
    int i = blockIdx.x, tid = threadIdx.x;
    float v[8]; float sum = 0.f, sq = 0.f;
#pragma unroll
    for (int j = 0; j < 8; j++) {
        int n = tid + j * 256;
        float a = 0.f;
        for (int sp = 0; sp < ks; sp++) a += P[(size_t)sp * 65536 + i * 2048 + n];
        a += bias[n];
        v[j] = a; sum += a; sq += a * a;
    }
    if (last) {
#pragma unroll
        for (int j = 0; j < 8; j++) out[i * 2048 + tid + j * 256] = v[j];
        return;
    }
    float mu, rstd;
    ln_stats(sum, sq, red, tid, mu, rstd);
#pragma unroll
    for (int j = 0; j < 8; j++) {
        int n = tid + j * 256;
        s[i * 2048 + n] = v[j];
        y[i * 2048 + n] = (v[j] - mu) * rstd * g[n] + bt[n];
    }
}

// ================ scalar attention + cumsum (fused qkv split-K sum) ================
__global__ void attn_k(const float* __restrict__ P, float* __restrict__ imv, int ks) {
    const size_t ST = (size_t)32 * 6144;
    int h = blockIdx.x;
    int tid = threadIdx.x;
    int w = tid >> 5, lane = tid & 31;
    __shared__ float rsa[32];

#pragma unroll
    for (int ii = 0; ii < 8; ii++) {
        int i = w * 8 + ii;
        size_t qb = (size_t)i * 6144 + h * 128 + lane * 4;
        float4 qa = make_float4(0.f, 0.f, 0.f, 0.f), ka = make_float4(0.f, 0.f, 0.f, 0.f);
        for (int sp = 0; sp < ks; sp++) {
            float4 q = *(const float4*)&P[sp * ST + qb];
            float4 k = *(const float4*)&P[sp * ST + qb + 2048];
            qa.x += q.x; qa.y += q.y; qa.z += q.z; qa.w += q.w;
            ka.x += k.x; ka.y += k.y; ka.z += k.z; ka.w += k.w;
        }
        float p = qa.x * ka.x + qa.y * ka.y + qa.z * ka.z + qa.w * ka.w;
#pragma unroll
        for (int off = 16; off; off >>= 1) p += __shfl_xor_sync(0xffffffffu, p, off);
        if (lane == 0) rsa[i] = p * 0.08838834764831845f;
    }
    __syncthreads();

    int d = tid;
    float run = 0.f;
#pragma unroll
    for (int i = 0; i < 32; i++) {
        size_t vb = (size_t)i * 6144 + 4096 + h * 128 + d;
        float vv = 0.f;
        for (int sp = 0; sp < ks; sp++) vv += P[sp * ST + vb];
        run += rsa[i] * vv;
        imv[i * 2048 + h * 128 + d] = run;
    }
}

// ================ launch ================
extern "C" void kernel_launch(void* const* d_in, const int* in_sizes, int n_in,
                              void* d_out, int out_size)
{
    const float* x      = (const float*)d_in[0];
    const float* weight = (const float*)d_in[1];
    const float* Wqkv   = (const float*)d_in[2];
    const float* Wo     = (const float*)d_in[3];
    const float* ln1_g  = (const float*)d_in[4];
    const float* ln1_b  = (const float*)d_in[5];
    const float* ln2_g  = (const float*)d_in[6];
    const float* ln2_b  = (const float*)d_in[7];
    const float* fc1_w  = (const float*)d_in[8];
    const float* fc1_b  = (const float*)d_in[9];
    const float* fc2_w  = (const float*)d_in[10];
    const float* fc2_b  = (const float*)d_in[11];
    float* out = (float*)d_out;

    float *p_altx, *p_s, *p_y, *p_imv, *p_h, *p_part;
    cudaGetSymbolAddress((void**)&p_altx, g_altx);
    cudaGetSymbolAddress((void**)&p_s,    g_s);
    cudaGetSymbolAddress((void**)&p_y,    g_y);
    cudaGetSymbolAddress((void**)&p_imv,  g_imv);
    cudaGetSymbolAddress((void**)&p_h,    g_h);
    cudaGetSymbolAddress((void**)&p_part, g_part);

    avg_k<<<256, 256>>>(x, p_altx);

    // s = weight @ altx^T + sinbias ; y = LN1(s)   (N=2048, ks=16, kc=128)
    gemm_mma<<<dim3(8, 16), 256>>>(p_altx, weight, p_part, MD, MD, 128);
    postA_k<<<32, 256>>>(p_part, p_s, p_y, ln1_g, ln1_b, 16);

    for (int a = 0; a < 3; a++) {
        // qkv   (N=6144, ks=8, kc=256)
        gemm_mma<<<dim3(24, 8), 256>>>(p_y, Wqkv + (size_t)a * NQKV * MD,
                                       p_part, NQKV, MD, 256);
        attn_k<<<16, 128>>>(p_part, p_imv, 8);

        // Wo    (N=2048, ks=16, kc=128)
        gemm_mma<<<dim3(8, 16), 256>>>(p_imv, Wo + (size_t)a * MD * MD,
                                       p_part, MD, MD, 128);
        postB_k<<<32, 256>>>(p_part, p_s, ln2_g, ln2_b, 16);

        // fc1   (N=8192, ks=8, kc=256)
        gemm_mma<<<dim3(32, 8), 256>>>(p_s, fc1_w, p_part, NFF, MD, 256);
        postC_k<<<256, 256>>>(p_part, p_h, fc1_b, 8);

        // fc2   (N=2048, K=8192, ks=32, kc=256)
        gemm_mma<<<dim3(8, 32), 256>>>(p_h, fc2_w, p_part, MD, NFF, 256);
        postD_k<<<32, 256>>>(p_part, p_s, p_y, fc2_b, ln1_g, ln1_b, out, a == 2, 32);
    }
}